// round 17
// baseline (speedup 1.0000x reference)
#include <cuda_runtime.h>
#include <cuda_fp16.h>

#define BB 2
#define CC 256
#define HH 200
#define WW 200
#define KK 1000
#define NSAMP 14   // POOLED * S = 7*2 per axis
#define NBINS 49
#define CHALF 128  // channels per block (half of C)

// NHWC fp16 scratch: [B][H][W][C]. Viewed as uint4 = 8 halves (8 channels).
// 2*200*200*256 * 2B = 40.96 MB -> fully L2-resident during gather.
__device__ uint4 g_xt[(size_t)BB * HH * WW * (CC / 8)];

// ---------------------------------------------------------------------------
// Transpose+convert v3: x[B,C,H,W] f32 -> g_xt[B,H,W,C] f16.
// One block per (b, h, 64-channel group): grid (1, 4, 400), block (32,8).
// Read phase: each of 64 channel-rows is read as a FULL 200-float run
// (800B contiguous DRAM runs vs 128B in v1 -> better row locality).
// SMEM: __half tile[64][256] with XOR swizzle col = w ^ 4*oct:
//   store: per-instr c fixed -> constant XOR = bank permutation (clean);
//   read:  lanes (oct 0..7, wl 0..3): low bits wl ^ 4*oct cover all 32
//          combos -> conflict-free.
// Write phase: pack 8 channels -> uint4, STG.128; per instr 8 oct x 4 w =
// four dense 128B runs. __float2half_rn per element == v1 rounding
// (bit-identical g_xt).
// ---------------------------------------------------------------------------
__global__ __launch_bounds__(256) void transpose_f16_kernel(
    const float* __restrict__ x) {
    __shared__ __half tile[64][256];  // 32 KB
    int bh = blockIdx.z;
    int b = bh / HH, h = bh % HH;
    int c0 = blockIdx.y * 64;
    int tx = threadIdx.x, ty = threadIdx.y;

    // Read + convert: c_local = ty + 8*ii (oct == ii), w = tx + 32*k.
#pragma unroll
    for (int ii = 0; ii < 8; ii++) {
        int cl = ty + 8 * ii;           // 0..63, octet = ii
        const float* row = x + (((size_t)b * CC + c0 + cl) * HH + h) * WW;
        int xorv = 4 * ii;
#pragma unroll
        for (int k = 0; k < 7; k++) {
            int w = tx + 32 * k;
            if (w < WW)
                tile[cl][w ^ xorv] = __float2half_rn(row[w]);
        }
    }
    __syncthreads();

    // Pack + store: t -> (oct = t&7, wl = t>>3); w = wl + 32*k.
    int t = ty * 32 + tx;
    int oct = t & 7;
    int wl  = t >> 3;
    uint4* dst = g_xt + (((size_t)b * HH + h) * WW) * (CC / 8) + (c0 >> 3) + oct;
#pragma unroll
    for (int k = 0; k < 7; k++) {
        int w = wl + 32 * k;
        if (w < WW) {
            int col = w ^ (4 * oct);
            unsigned short u0 = __half_as_ushort(tile[8 * oct + 0][col]);
            unsigned short u1 = __half_as_ushort(tile[8 * oct + 1][col]);
            unsigned short u2 = __half_as_ushort(tile[8 * oct + 2][col]);
            unsigned short u3 = __half_as_ushort(tile[8 * oct + 3][col]);
            unsigned short u4 = __half_as_ushort(tile[8 * oct + 4][col]);
            unsigned short u5 = __half_as_ushort(tile[8 * oct + 5][col]);
            unsigned short u6 = __half_as_ushort(tile[8 * oct + 6][col]);
            unsigned short u7 = __half_as_ushort(tile[8 * oct + 7][col]);
            uint4 v;
            v.x = (unsigned int)u0 | ((unsigned int)u1 << 16);
            v.y = (unsigned int)u2 | ((unsigned int)u3 << 16);
            v.z = (unsigned int)u4 | ((unsigned int)u5 << 16);
            v.w = (unsigned int)u6 | ((unsigned int)u7 << 16);
            dst[(size_t)w * (CC / 8)] = v;
        }
    }
}

// ---------------------------------------------------------------------------
// RoIAlign gather: one block per (ROI, channel-half). grid = (1000, 2),
// 256 threads. FROZEN at measured-best config (regs 64 via (256,4)).
//   qloc = (t & 15) -> 8-channel octet within the half (uint4 = 8 fp16 ch)
//   g    = (t >> 4) -> bin group (16 groups stride over 49 bins)
// 196 sample-point weight quads precomputed into s_wtab (1 LDS.128/point).
// Per point: 4 corner uint4 loads, fp16 HMUL2/HFMA2 4-corner combine, one
// f16x2->f32 convert, fp32 accumulation (1/4 averaging folded into weights).
// Output half-tile [128][49] f32 staged in SMEM, coalesced float4 flush.
// Reg/MLP curve measured: 40r/6blk=45.9us, 48r/5blk=38.0us, 64r/4blk=36.4us.
// ---------------------------------------------------------------------------
__global__ __launch_bounds__(256, 4) void roialign_kernel(
    const float* __restrict__ rois, float* __restrict__ out) {
    int k = blockIdx.x;
    int half = blockIdx.y;
    __shared__ int   s_lo[2 * NSAMP], s_hi[2 * NSAMP];
    __shared__ float s_w0[2 * NSAMP], s_w1[2 * NSAMP];
    __shared__ int   s_b;
    __shared__ uint4 s_wtab[NSAMP * NSAMP];       // 196 * 16B = 3136 B
    __shared__ float4 out_s4[CHALF * NBINS / 4];  // 25088 B, 16B-aligned
    float* out_s = (float*)out_s4;

    int t = threadIdx.x;
    if (t == 0) s_b = (int)rois[k * 5];
    if (t < 2 * NSAMP) {
        // t in [0, NSAMP): y axis; t in [NSAMP, 2*NSAMP): x axis
        int isx = (t >= NSAMP) ? 1 : 0;
        int idx = isx ? t - NSAMP : t;
        float r1 = rois[k * 5 + (isx ? 1 : 2)];
        float r2 = rois[k * 5 + (isx ? 3 : 4)];
        int limit = isx ? WW : HH;
        float start = r1 * 0.25f - 0.5f;          // SPATIAL_SCALE, aligned offset
        float endv  = r2 * 0.25f - 0.5f;
        float binsz = (endv - start) * (1.0f / 7.0f);
        int p  = idx >> 1;                        // pooled bin
        int si = idx & 1;                         // sample within bin
        float coord = start + ((float)p + ((float)si + 0.5f) * 0.5f) * binsz;
        // validity folded into weight; 0.5 per axis => 1/4 grid average total
        float validf = (coord >= -1.0f && coord <= (float)limit) ? 0.5f : 0.0f;
        float cc = fmaxf(coord, 0.0f);
        int low0 = (int)floorf(cc);
        int cap  = (low0 >= limit - 1) ? 1 : 0;
        int low  = cap ? limit - 1 : low0;
        int high = cap ? limit - 1 : low0 + 1;
        if (cap) cc = (float)low;
        float l = cc - (float)low;
        float h = 1.0f - l;
        s_lo[t] = low;
        s_hi[t] = high;
        s_w0[t] = h * validf;
        s_w1[t] = l * validf;
    }
    __syncthreads();

    // Precompute all 196 point-weight quads (broadcast half2 each).
    if (t < NSAMP * NSAMP) {
        int ys = t / NSAMP, xs = t - (t / NSAMP) * NSAMP;
        float wy0 = s_w0[ys], wy1 = s_w1[ys];
        float wx0 = s_w0[NSAMP + xs], wx1 = s_w1[NSAMP + xs];
        __half2 h00 = __float2half2_rn(wy0 * wx0);
        __half2 h01 = __float2half2_rn(wy0 * wx1);
        __half2 h10 = __float2half2_rn(wy1 * wx0);
        __half2 h11 = __float2half2_rn(wy1 * wx1);
        uint4 v;
        v.x = *(unsigned int*)&h00;
        v.y = *(unsigned int*)&h01;
        v.z = *(unsigned int*)&h10;
        v.w = *(unsigned int*)&h11;
        s_wtab[t] = v;
    }
    __syncthreads();

    int b = s_b;
    const uint4* __restrict__ basev = g_xt + (size_t)b * (HH * WW) * (CC / 8);
    int qloc = t & 15;
    int g = t >> 4;
    int q = half * (CHALF / 8) + qloc;  // global 8-channel octet

    for (int bin = g; bin < NBINS; bin += 16) {
        int ph = bin / 7;
        int pw = bin - ph * 7;
        float acc0 = 0.f, acc1 = 0.f, acc2 = 0.f, acc3 = 0.f;
        float acc4 = 0.f, acc5 = 0.f, acc6 = 0.f, acc7 = 0.f;
#pragma unroll
        for (int j = 0; j < 2; j++) {
            int ys = 2 * ph + j;
            int ry0 = s_lo[ys] * WW;
            int ry1 = s_hi[ys] * WW;
#pragma unroll
            for (int i = 0; i < 2; i++) {
                int xs = 2 * pw + i;
                int x0 = s_lo[NSAMP + xs], x1 = s_hi[NSAMP + xs];
                uint4 wv = s_wtab[ys * NSAMP + xs];
                __half2 h00 = *(__half2*)&wv.x;
                __half2 h01 = *(__half2*)&wv.y;
                __half2 h10 = *(__half2*)&wv.z;
                __half2 h11 = *(__half2*)&wv.w;
                uint4 u00 = basev[(ry0 + x0) * (CC / 8) + q];
                uint4 u01 = basev[(ry0 + x1) * (CC / 8) + q];
                uint4 u10 = basev[(ry1 + x0) * (CC / 8) + q];
                uint4 u11 = basev[(ry1 + x1) * (CC / 8) + q];
                const __half2* p00 = (const __half2*)&u00;
                const __half2* p01 = (const __half2*)&u01;
                const __half2* p10 = (const __half2*)&u10;
                const __half2* p11 = (const __half2*)&u11;
                // 4-corner convex combine in fp16, one convert, f32 accumulate
                __half2 hv0 = __hmul2(p00[0], h00);
                __half2 hv1 = __hmul2(p00[1], h00);
                __half2 hv2 = __hmul2(p00[2], h00);
                __half2 hv3 = __hmul2(p00[3], h00);
                hv0 = __hfma2(p01[0], h01, hv0);
                hv1 = __hfma2(p01[1], h01, hv1);
                hv2 = __hfma2(p01[2], h01, hv2);
                hv3 = __hfma2(p01[3], h01, hv3);
                hv0 = __hfma2(p10[0], h10, hv0);
                hv1 = __hfma2(p10[1], h10, hv1);
                hv2 = __hfma2(p10[2], h10, hv2);
                hv3 = __hfma2(p10[3], h10, hv3);
                hv0 = __hfma2(p11[0], h11, hv0);
                hv1 = __hfma2(p11[1], h11, hv1);
                hv2 = __hfma2(p11[2], h11, hv2);
                hv3 = __hfma2(p11[3], h11, hv3);
                float2 f0 = __half22float2(hv0);
                float2 f1 = __half22float2(hv1);
                float2 f2 = __half22float2(hv2);
                float2 f3 = __half22float2(hv3);
                acc0 += f0.x; acc1 += f0.y;
                acc2 += f1.x; acc3 += f1.y;
                acc4 += f2.x; acc5 += f2.y;
                acc6 += f3.x; acc7 += f3.y;
            }
        }
        int cb = qloc * 8;  // channel within half
        out_s[(cb + 0) * NBINS + bin] = acc0;
        out_s[(cb + 1) * NBINS + bin] = acc1;
        out_s[(cb + 2) * NBINS + bin] = acc2;
        out_s[(cb + 3) * NBINS + bin] = acc3;
        out_s[(cb + 4) * NBINS + bin] = acc4;
        out_s[(cb + 5) * NBINS + bin] = acc5;
        out_s[(cb + 6) * NBINS + bin] = acc6;
        out_s[(cb + 7) * NBINS + bin] = acc7;
    }
    __syncthreads();

    // Coalesced flush: this half's out region is contiguous (128*49 f32,
    // 25088 B; offsets are multiples of 16B).
    float4* outk = (float4*)(out + ((size_t)k * CC + half * CHALF) * NBINS);
    for (int i = t; i < CHALF * NBINS / 4; i += 256) outk[i] = out_s4[i];
}

extern "C" void kernel_launch(void* const* d_in, const int* in_sizes, int n_in,
                              void* d_out, int out_size) {
    const float* x    = (const float*)d_in[0];
    const float* rois = (const float*)d_in[1];
    float* out = (float*)d_out;

    // 1) NHWC fp16 transpose v3: full-row reads, grid (1, 4, 400)
    dim3 tb(32, 8);
    dim3 tg(1, CC / 64, BB * HH);
    transpose_f16_kernel<<<tg, tb>>>(x);

    // 2) RoIAlign gather: one block per (ROI, channel-half)
    roialign_kernel<<<dim3(KK, 2), 256>>>(rois, out);
}